// round 12
// baseline (speedup 1.0000x reference)
#include <cuda_runtime.h>
#include <math.h>

// 256^3 grid, 1 byte/voxel thermometer code: level L = 7 - d2 (d2 in 0..6),
// byte = (1<<L)-1. atomicOr of thermometer codes == thermometer of max level.
#define GDIM     256
#define VQUADS   (GDIM*GDIM*GDIM/16)   // 1,048,576 uint4 per grid
#define NBLOCKS  512
#define NTHREADS 256
#define TOTALT   (NBLOCKS*NTHREADS)    // 131072 threads
#define KITER    (VQUADS/TOTALT)       // 8 quads per thread per grid (exact)

__device__ uint4 g_src[VQUADS];        // zero at load; re-zeroed in phase 2
__device__ uint4 g_tgt[VQUADS];
__device__ float g_part[NBLOCKS];
__device__ unsigned int g_count;       // last-block-done (self-resetting)
__device__ unsigned int g_bar;         // MONOTONIC grid barrier (never reset)

// 5-byte row patterns (dz = -2..2 in bytes 0..4), indexed by s2 = d0^2 + d1^2.
__device__ __constant__ unsigned long long c_PAT[8] = {
    0x00000007'3F7F3F07ULL,  // s2=0
    0x00000003'1F3F1F03ULL,  // s2=1
    0x00000001'0F1F0F01ULL,  // s2=2
    0ULL,
    0x00000000'03070300ULL,  // s2=4
    0x00000000'01030100ULL,  // s2=5
    0ULL, 0ULL
};

__global__ void __launch_bounds__(NTHREADS)
fused_kernel(const float* __restrict__ src,
             const float* __restrict__ tgt,
             const float* __restrict__ ox,
             const float* __restrict__ oy,
             const float* __restrict__ oz,
             const float* __restrict__ vx,
             int N,
             float* __restrict__ out)
{
    __shared__ unsigned long long spat[8];
    __shared__ float s2tab[256];
    __shared__ float ctab[256];
    __shared__ float wsum[NTHREADS / 32];
    __shared__ double wsumd[NTHREADS / 32];
    __shared__ bool  isLast;

    const float KK = (float)((3.14159265358979323846 / 3.5) * (3.14159265358979323846 / 3.5));
    int tid  = threadIdx.x;
    int gtid = blockIdx.x * NTHREADS + tid;

    if (tid < 8) spat[tid] = c_PAT[tid];
    __syncthreads();

    // ---------------- Phase 1: splat (one virtual thread per (atom, d0 slice)) ----
    {
        float v   = vx[0];
        float oxv = ox[0], oyv = oy[0], ozv = oz[0];
        int total = 2 * N * 5;
        for (int t = gtid; t < total; t += TOTALT) {
            int a  = t / 5;
            int d0 = t - a * 5 - 2;
            bool isSrc = (a < N);
            const float* c = isSrc ? src : tgt;
            unsigned long long* grid = (unsigned long long*)(isSrc ? g_src : g_tgt);
            int n = isSrc ? a : (a - N);

            // IEEE f32 divide so floor matches the reference bit-exactly.
            float fx = __fdiv_rn(c[n]         - oxv, v);
            float fy = __fdiv_rn(c[N + n]     - oyv, v);
            float fz = __fdiv_rn(c[2 * N + n] - ozv, v);
            int i0 = (int)floorf(fx);
            int i1 = (int)floorf(fy);
            int i2 = (int)floorf(fz);
            if ((unsigned)i0 > 255u || (unsigned)i1 > 255u || (unsigned)i2 > 255u) continue;

            int j0 = i0 + d0;
            if ((unsigned)j0 > 255u) continue;
            int d02 = d0 * d0;

            // z-clip shared across this slice's rows
            int start = i2 - 2;
            unsigned rsh = 0;
            if (start < 0) { rsh = (unsigned)(-start) * 8u; start = 0; }
            unsigned long long msk = ~0ULL;
            int avail = 256 - start;
            if (avail < 5) msk = (1ULL << (avail * 8)) - 1ULL;
            unsigned shl   = (unsigned)(start & 7) * 8u;
            unsigned qoff  = (unsigned)(start >> 3);
            unsigned rbase = ((unsigned)(j0 * 256 + i1)) * 32u + qoff;

#pragma unroll
            for (int d1 = -2; d1 <= 2; d1++) {
                int s2 = d02 + d1 * d1;
                if (s2 >= 8) continue;
                int j1 = i1 + d1;
                if ((unsigned)j1 > 255u) continue;
                unsigned long long p = (spat[s2] >> rsh) & msk;
                __uint128_t sv = (__uint128_t)p << shl;
                unsigned long long lo = (unsigned long long)sv;
                unsigned long long hi = (unsigned long long)(sv >> 64);
                unsigned q = rbase + (unsigned)d1 * 32u;
                if (lo) atomicOr(&grid[q], lo);
                if (hi) atomicOr(&grid[q + 1], hi);
            }
        }
    }

    // ---------------- Table init (overlaps other blocks' splat tails) -------------
    for (int i = tid; i < 256; i += NTHREADS) { s2tab[i] = 0.0f; ctab[i] = 0.0f; }
    __syncthreads();
    if (tid < 64) {
        int a = tid >> 3, b = tid & 7;
        int idx = (1 << a) + (1 << b) - 2;          // thermo(a)+thermo(b), perfect hash
        float g1 = a ? expf(-2.0f * KK * (float)(7 - a)) : 0.0f;
        float g2 = b ? expf(-2.0f * KK * (float)(7 - b)) : 0.0f;
        s2tab[idx] = g1 + g2;
        ctab[idx]  = (a && b) ? expf(-KK * (float)(14 - a - b)) : 0.0f;
    }

    // ---------------- Grid barrier (monotonic counter, graph-replay safe) ---------
    __threadfence();                     // publish this thread's REDs
    __syncthreads();                     // all block threads published + tables ready
    if (tid == 0) {
        atomicAdd(&g_bar, 1u);
        while ((*(volatile unsigned int*)&g_bar & (NBLOCKS - 1)) != 0u)
            __nanosleep(64);
    }
    __syncthreads();

    // ---------------- Phase 2: reduce + zero ------------------------------------
    // src^2: per halfword, key = b0+b1 = 2^L1+2^L2-2 (perfect hash, symmetric
    // value) -> one LDS per 2 voxels; s2tab[0]=0 makes empty words free-safe.
    // cross: per byte, key = thermo(Ls)+thermo(Lt); single-sided keys land on
    // LUT zeros -> branchless vadd4 decode on the rare taken path.
    float a0 = 0.0f, a1 = 0.0f, a2 = 0.0f, a3 = 0.0f;
    const uint4 z4 = make_uint4(0u, 0u, 0u, 0u);

#pragma unroll
    for (int k = 0; k < KITER; k += 2) {
        int iA = gtid + k * TOTALT;
        int iB = gtid + (k + 1) * TOTALT;
        uint4 s0 = g_src[iA];
        uint4 s1 = g_src[iB];
        uint4 t0 = g_tgt[iA];
        uint4 t1 = g_tgt[iB];

        unsigned sw[8] = { s0.x, s0.y, s0.z, s0.w, s1.x, s1.y, s1.z, s1.w };
        unsigned tw[8] = { t0.x, t0.y, t0.z, t0.w, t1.x, t1.y, t1.z, t1.w };

        // branchless src^2 term
#pragma unroll
        for (int l = 0; l < 8; l += 2) {
            unsigned k0 = __dp4a(sw[l],     0x00000101u, 0u);
            unsigned k1 = __dp4a(sw[l],     0x01010000u, 0u);
            unsigned k2 = __dp4a(sw[l + 1], 0x00000101u, 0u);
            unsigned k3 = __dp4a(sw[l + 1], 0x01010000u, 0u);
            a0 += s2tab[k0];
            a1 += s2tab[k1];
            a2 += s2tab[k2];
            a3 += s2tab[k3];
        }

        // cross term, rare
        unsigned uA = (sw[0] & tw[0]) | (sw[1] & tw[1]) | (sw[2] & tw[2]) | (sw[3] & tw[3]);
        unsigned uB = (sw[4] & tw[4]) | (sw[5] & tw[5]) | (sw[6] & tw[6]) | (sw[7] & tw[7]);
        if (uA | uB) {
#pragma unroll
            for (int l = 0; l < 8; l++) {
                unsigned kw = __vaddus4(sw[l], tw[l]);
                a0 -= ctab[kw & 255u];
                a1 -= ctab[(kw >> 8)  & 255u];
                a2 -= ctab[(kw >> 16) & 255u];
                a3 -= ctab[kw >> 24];
            }
        }

        // zero-stores for next replay (predicated, ~80% taken)
        if (sw[0] | sw[1] | sw[2] | sw[3]) g_src[iA] = z4;
        if (sw[4] | sw[5] | sw[6] | sw[7]) g_src[iB] = z4;
        if (tw[0] | tw[1] | tw[2] | tw[3]) g_tgt[iA] = z4;
        if (tw[4] | tw[5] | tw[6] | tw[7]) g_tgt[iB] = z4;
    }

    // ---------------- Block partial + last-block final sum ----------------------
    float acc = (a0 + a1) + (a2 + a3);
#pragma unroll
    for (int off = 16; off > 0; off >>= 1)
        acc += __shfl_down_sync(0xFFFFFFFFu, acc, off);
    int warp = tid >> 5;
    if ((tid & 31) == 0) wsum[warp] = acc;
    __syncthreads();
    if (tid == 0) {
        float b = 0.0f;
#pragma unroll
        for (int wdx = 0; wdx < NTHREADS / 32; wdx++) b += wsum[wdx];
        g_part[blockIdx.x] = b;
        __threadfence();
        unsigned vdone = atomicAdd(&g_count, 1u);
        isLast = (vdone == (unsigned)NBLOCKS - 1u);
        if (isLast) g_count = 0u;     // reset for next replay
    }
    __syncthreads();

    if (isLast) {
        double a = 0.0;
        for (int i = tid; i < NBLOCKS; i += NTHREADS)
            a += (double)g_part[i];
#pragma unroll
        for (int off = 16; off > 0; off >>= 1)
            a += __shfl_down_sync(0xFFFFFFFFu, a, off);
        if ((tid & 31) == 0) wsumd[warp] = a;
        __syncthreads();
        if (tid == 0) {
            double tot = 0.0;
#pragma unroll
            for (int wdx = 0; wdx < NTHREADS / 32; wdx++) tot += wsumd[wdx];
            out[0] = (float)tot;
        }
    }
}

extern "C" void kernel_launch(void* const* d_in, const int* in_sizes, int n_in,
                              void* d_out, int out_size)
{
    const float* src = (const float*)d_in[0];
    const float* tgt = (const float*)d_in[1];
    const float* ox  = (const float*)d_in[2];
    const float* oy  = (const float*)d_in[3];
    const float* oz  = (const float*)d_in[4];
    const float* vx  = (const float*)d_in[5];
    int N = in_sizes[0] / 3;

    fused_kernel<<<NBLOCKS, NTHREADS>>>(src, tgt, ox, oy, oz, vx, N, (float*)d_out);
}

// round 14
// speedup vs baseline: 1.0094x; 1.0094x over previous
#include <cuda_runtime.h>
#include <math.h>

// 256^3 grid, 1 byte/voxel thermometer code: level L = 7 - d2 (d2 in 0..6),
// byte = (1<<L)-1. atomicOr of thermometer codes == thermometer of max level.
#define GDIM     256
#define VQUADS   (GDIM*GDIM*GDIM/16)   // 1,048,576 uint4 per grid
#define NBLOCKS  512
#define NTHREADS 512
#define TOTALT   (NBLOCKS*NTHREADS)    // 262144 threads
#define KITER    (VQUADS/TOTALT)       // 4 quads per thread per grid (exact)

__device__ uint4 g_src[VQUADS];        // zero at load; re-zeroed in phase 2
__device__ uint4 g_tgt[VQUADS];
__device__ float g_part[NBLOCKS];
__device__ unsigned int g_count;       // last-block-done (self-resetting)
__device__ unsigned int g_bar;         // MONOTONIC grid barrier (never reset)

// 5-byte row patterns (dz = -2..2 in bytes 0..4), indexed by s2 = d0^2 + d1^2.
__device__ __constant__ unsigned long long c_PAT[8] = {
    0x00000007'3F7F3F07ULL,  // s2=0
    0x00000003'1F3F1F03ULL,  // s2=1
    0x00000001'0F1F0F01ULL,  // s2=2
    0ULL,
    0x00000000'03070300ULL,  // s2=4
    0x00000000'01030100ULL,  // s2=5
    0ULL, 0ULL
};

__global__ void __launch_bounds__(NTHREADS, 4)
fused_kernel(const float* __restrict__ src,
             const float* __restrict__ tgt,
             const float* __restrict__ ox,
             const float* __restrict__ oy,
             const float* __restrict__ oz,
             const float* __restrict__ vx,
             int N,
             float* __restrict__ out)
{
    __shared__ unsigned long long spat[8];
    __shared__ float s2tab[256];
    __shared__ float ctab[256];
    __shared__ float wsum[NTHREADS / 32];
    __shared__ double wsumd[NTHREADS / 32];
    __shared__ bool  isLast;

    const float KK = (float)((3.14159265358979323846 / 3.5) * (3.14159265358979323846 / 3.5));
    int tid  = threadIdx.x;
    int gtid = blockIdx.x * NTHREADS + tid;

    if (tid < 8) spat[tid] = c_PAT[tid];
    __syncthreads();

    // ---- Phase 1: splat — one thread per (atom, d0 slice); 2N*5 <= TOTALT ----
    {
        int total = 2 * N * 5;
        int t = gtid;
        if (t < total) {
            float v   = vx[0];
            float oxv = ox[0], oyv = oy[0], ozv = oz[0];
            int a  = t / 5;
            int d0 = t - a * 5 - 2;
            bool isSrc = (a < N);
            const float* c = isSrc ? src : tgt;
            unsigned long long* grid = (unsigned long long*)(isSrc ? g_src : g_tgt);
            int n = isSrc ? a : (a - N);

            // IEEE f32 divide so floor matches the reference bit-exactly.
            float fx = __fdiv_rn(c[n]         - oxv, v);
            float fy = __fdiv_rn(c[N + n]     - oyv, v);
            float fz = __fdiv_rn(c[2 * N + n] - ozv, v);
            int i0 = (int)floorf(fx);
            int i1 = (int)floorf(fy);
            int i2 = (int)floorf(fz);
            int j0 = i0 + d0;
            bool ok = (unsigned)i0 <= 255u && (unsigned)i1 <= 255u &&
                      (unsigned)i2 <= 255u && (unsigned)j0 <= 255u;
            if (ok) {
                int d02 = d0 * d0;
                // z-clip shared across this slice's rows
                int start = i2 - 2;
                unsigned rsh = 0;
                if (start < 0) { rsh = (unsigned)(-start) * 8u; start = 0; }
                unsigned long long msk = ~0ULL;
                int avail = 256 - start;
                if (avail < 5) msk = (1ULL << (avail * 8)) - 1ULL;
                unsigned shl   = (unsigned)(start & 7) * 8u;
                unsigned qoff  = (unsigned)(start >> 3);
                unsigned rbase = ((unsigned)(j0 * 256 + i1)) * 32u + qoff;

#pragma unroll
                for (int d1 = -2; d1 <= 2; d1++) {
                    int s2 = d02 + d1 * d1;
                    if (s2 >= 8) continue;
                    int j1 = i1 + d1;
                    if ((unsigned)j1 > 255u) continue;
                    unsigned long long p = (spat[s2] >> rsh) & msk;
                    __uint128_t sv = (__uint128_t)p << shl;
                    unsigned long long lo = (unsigned long long)sv;
                    unsigned long long hi = (unsigned long long)(sv >> 64);
                    unsigned q = rbase + (unsigned)d1 * 32u;
                    if (lo) atomicOr(&grid[q], lo);
                    if (hi) atomicOr(&grid[q + 1], hi);
                }
            }
        }
    }

    // ---- Table init (overlaps other blocks' splat tails) ----
    for (int i = tid; i < 256; i += NTHREADS) { s2tab[i] = 0.0f; ctab[i] = 0.0f; }
    __syncthreads();
    if (tid < 64) {
        int a = tid >> 3, b = tid & 7;
        int idx = (1 << a) + (1 << b) - 2;          // thermo(a)+thermo(b), perfect hash
        float g1 = a ? expf(-2.0f * KK * (float)(7 - a)) : 0.0f;
        float g2 = b ? expf(-2.0f * KK * (float)(7 - b)) : 0.0f;
        s2tab[idx] = g1 + g2;
        ctab[idx]  = (a && b) ? expf(-KK * (float)(14 - a - b)) : 0.0f;
    }

    // ---- Grid barrier (monotonic counter, graph-replay safe; 592 slots >= 512) ----
    __threadfence();                     // publish this thread's REDs
    __syncthreads();                     // all block threads published + tables ready
    if (tid == 0) {
        atomicAdd(&g_bar, 1u);
        while ((*(volatile unsigned int*)&g_bar & (NBLOCKS - 1)) != 0u)
            __nanosleep(64);
    }
    __syncthreads();

    // ---- Phase 2: reduce + zero ----
    // src^2: per halfword, key = b0+b1 = 2^L1+2^L2-2 (perfect hash, symmetric
    // value) -> one LDS per 2 voxels; s2tab[0]=0 makes empty words free-safe.
    // cross: per byte, key = thermo(Ls)+thermo(Lt); single-sided keys land on
    // LUT zeros -> branchless vadd4 decode on the rare taken path.
    float a0 = 0.0f, a1 = 0.0f, a2 = 0.0f, a3 = 0.0f;
    const uint4 z4 = make_uint4(0u, 0u, 0u, 0u);

#pragma unroll
    for (int k = 0; k < KITER; k += 2) {
        int iA = gtid + k * TOTALT;
        int iB = gtid + (k + 1) * TOTALT;
        uint4 s0 = g_src[iA];
        uint4 s1 = g_src[iB];
        uint4 t0 = g_tgt[iA];
        uint4 t1 = g_tgt[iB];

        unsigned sw[8] = { s0.x, s0.y, s0.z, s0.w, s1.x, s1.y, s1.z, s1.w };
        unsigned tw[8] = { t0.x, t0.y, t0.z, t0.w, t1.x, t1.y, t1.z, t1.w };

        // branchless src^2 term
#pragma unroll
        for (int l = 0; l < 8; l += 2) {
            unsigned k0 = __dp4a(sw[l],     0x00000101u, 0u);
            unsigned k1 = __dp4a(sw[l],     0x01010000u, 0u);
            unsigned k2 = __dp4a(sw[l + 1], 0x00000101u, 0u);
            unsigned k3 = __dp4a(sw[l + 1], 0x01010000u, 0u);
            a0 += s2tab[k0];
            a1 += s2tab[k1];
            a2 += s2tab[k2];
            a3 += s2tab[k3];
        }

        // cross term, rare
        unsigned uA = (sw[0] & tw[0]) | (sw[1] & tw[1]) | (sw[2] & tw[2]) | (sw[3] & tw[3]);
        unsigned uB = (sw[4] & tw[4]) | (sw[5] & tw[5]) | (sw[6] & tw[6]) | (sw[7] & tw[7]);
        if (uA | uB) {
#pragma unroll
            for (int l = 0; l < 8; l++) {
                unsigned kw = __vaddus4(sw[l], tw[l]);
                a0 -= ctab[kw & 255u];
                a1 -= ctab[(kw >> 8)  & 255u];
                a2 -= ctab[(kw >> 16) & 255u];
                a3 -= ctab[kw >> 24];
            }
        }

        // zero-stores for next replay (predicated)
        if (sw[0] | sw[1] | sw[2] | sw[3]) g_src[iA] = z4;
        if (sw[4] | sw[5] | sw[6] | sw[7]) g_src[iB] = z4;
        if (tw[0] | tw[1] | tw[2] | tw[3]) g_tgt[iA] = z4;
        if (tw[4] | tw[5] | tw[6] | tw[7]) g_tgt[iB] = z4;
    }

    // ---- Block partial + last-block final sum ----
    float acc = (a0 + a1) + (a2 + a3);
#pragma unroll
    for (int off = 16; off > 0; off >>= 1)
        acc += __shfl_down_sync(0xFFFFFFFFu, acc, off);
    int warp = tid >> 5;
    if ((tid & 31) == 0) wsum[warp] = acc;
    __syncthreads();
    if (tid == 0) {
        float b = 0.0f;
#pragma unroll
        for (int wdx = 0; wdx < NTHREADS / 32; wdx++) b += wsum[wdx];
        g_part[blockIdx.x] = b;
        __threadfence();
        unsigned vdone = atomicAdd(&g_count, 1u);
        isLast = (vdone == (unsigned)NBLOCKS - 1u);
        if (isLast) g_count = 0u;     // reset for next replay
    }
    __syncthreads();

    if (isLast) {
        double a = (tid < NBLOCKS) ? (double)g_part[tid] : 0.0;
#pragma unroll
        for (int off = 16; off > 0; off >>= 1)
            a += __shfl_down_sync(0xFFFFFFFFu, a, off);
        if ((tid & 31) == 0) wsumd[warp] = a;
        __syncthreads();
        if (tid == 0) {
            double tot = 0.0;
#pragma unroll
            for (int wdx = 0; wdx < NTHREADS / 32; wdx++) tot += wsumd[wdx];
            out[0] = (float)tot;
        }
    }
}

extern "C" void kernel_launch(void* const* d_in, const int* in_sizes, int n_in,
                              void* d_out, int out_size)
{
    const float* src = (const float*)d_in[0];
    const float* tgt = (const float*)d_in[1];
    const float* ox  = (const float*)d_in[2];
    const float* oy  = (const float*)d_in[3];
    const float* oz  = (const float*)d_in[4];
    const float* vx  = (const float*)d_in[5];
    int N = in_sizes[0] / 3;

    fused_kernel<<<NBLOCKS, NTHREADS>>>(src, tgt, ox, oy, oz, vx, N, (float*)d_out);
}

// round 15
// speedup vs baseline: 1.1774x; 1.1664x over previous
#include <cuda_runtime.h>
#include <math.h>

// 256^3 grid, 1 byte/voxel thermometer code: level L = 7 - d2 (d2 in 0..6),
// byte = (1<<L)-1. atomicOr of thermometer codes == thermometer of max level.
#define GDIM    256
#define VQUADS  (GDIM*GDIM*GDIM/16)  // 1,048,576 uint4 per grid
#define RBLOCKS 1024
#define RTHREADS 256
#define QPT     4                    // stages/quads per thread: VQUADS/(RBLOCKS*RTHREADS)

__device__ uint4 g_src[VQUADS];      // zero at load; re-zeroed by reduce each call
__device__ uint4 g_tgt[VQUADS];
__device__ float g_part[RBLOCKS];
__device__ unsigned int g_count;

// 5-byte row patterns (dz = -2..2 in bytes 0..4), indexed by s2 = d0^2 + d1^2.
__device__ __constant__ unsigned long long c_PAT[8] = {
    0x00000007'3F7F3F07ULL,  // s2=0
    0x00000003'1F3F1F03ULL,  // s2=1
    0x00000001'0F1F0F01ULL,  // s2=2
    0ULL,
    0x00000000'03070300ULL,  // s2=4
    0x00000000'01030100ULL,  // s2=5
    0ULL, 0ULL
};

__device__ __forceinline__ void cp16(void* smem, const void* gmem)
{
    unsigned saddr = (unsigned)__cvta_generic_to_shared(smem);
    asm volatile("cp.async.cg.shared.global [%0], [%1], 16;"
                 :: "r"(saddr), "l"(gmem) : "memory");
}
#define CP_COMMIT()  asm volatile("cp.async.commit_group;" ::: "memory")
#define CP_WAIT(n)   asm volatile("cp.async.wait_group %0;" :: "n"(n) : "memory")

// One thread per (atom, d0 slice): 2N*5 threads total.  (R5 version — fastest.)
__global__ void splat_kernel(const float* __restrict__ src,
                             const float* __restrict__ tgt,
                             const float* __restrict__ ox,
                             const float* __restrict__ oy,
                             const float* __restrict__ oz,
                             const float* __restrict__ vx,
                             int N)
{
    __shared__ unsigned long long spat[8];
    if (threadIdx.x < 8) spat[threadIdx.x] = c_PAT[threadIdx.x];
    __syncthreads();

    int t = blockIdx.x * blockDim.x + threadIdx.x;
    if (t >= 2 * N * 5) return;
    int a  = t / 5;
    int d0 = t - a * 5 - 2;
    bool isSrc = (a < N);
    const float* c = isSrc ? src : tgt;
    unsigned long long* grid = (unsigned long long*)(isSrc ? g_src : g_tgt);
    int n = isSrc ? a : (a - N);

    float v = vx[0];
    // IEEE f32 divide so floor matches the reference bit-exactly.
    float fx = __fdiv_rn(c[n]         - ox[0], v);
    float fy = __fdiv_rn(c[N + n]     - oy[0], v);
    float fz = __fdiv_rn(c[2 * N + n] - oz[0], v);
    int i0 = (int)floorf(fx);
    int i1 = (int)floorf(fy);
    int i2 = (int)floorf(fz);
    if ((unsigned)i0 > 255u || (unsigned)i1 > 255u || (unsigned)i2 > 255u) return;

    int j0 = i0 + d0;
    if ((unsigned)j0 > 255u) return;
    int d02 = d0 * d0;

    // z-clip shared across this thread's rows
    int start = i2 - 2;
    unsigned rsh = 0;
    if (start < 0) { rsh = (unsigned)(-start) * 8u; start = 0; }
    unsigned long long msk = ~0ULL;
    int avail = 256 - start;
    if (avail < 5) msk = (1ULL << (avail * 8)) - 1ULL;
    unsigned shl   = (unsigned)(start & 7) * 8u;
    unsigned qoff  = (unsigned)(start >> 3);
    unsigned rbase = ((unsigned)(j0 * 256 + i1)) * 32u + qoff;

#pragma unroll
    for (int d1 = -2; d1 <= 2; d1++) {
        int s2 = d02 + d1 * d1;
        if (s2 >= 8) continue;
        int j1 = i1 + d1;
        if ((unsigned)j1 > 255u) continue;
        unsigned long long p = (spat[s2] >> rsh) & msk;
        __uint128_t sv = (__uint128_t)p << shl;
        unsigned long long lo = (unsigned long long)sv;
        unsigned long long hi = (unsigned long long)(sv >> 64);
        unsigned q = rbase + (unsigned)d1 * 32u;
        if (lo) atomicOr(&grid[q], lo);
        if (hi) atomicOr(&grid[q + 1], hi);
    }
}

// Reduce + zero + final sum (last-block-done).
// Loads staged through smem via cp.async (LDGSTS): MLP=8 with zero register
// cost for in-flight data. Each thread reads back ONLY its own staged quads,
// so no block barrier is needed between wait_group and the LDS reads.
// src^2: per halfword, key = b0+b1 = 2^L1+2^L2-2 (perfect hash of the level
// pair, symmetric value) -> one LDS per 2 voxels; s2tab[0]=0 on empty words.
// cross: per byte, key = thermo(Ls)+thermo(Lt); single-sided keys land on
// LUT zeros -> branchless vadd4 decode on the rare taken path.
__global__ void __launch_bounds__(RTHREADS) reduce_kernel(float* __restrict__ out)
{
    __shared__ uint4 sbuf[QPT][2][RTHREADS];   // [stage][src/tgt][thread] = 32 KB
    __shared__ float s2tab[256];
    __shared__ float ctab[256];
    __shared__ float wsum[RTHREADS / 32];
    __shared__ double wsumd[RTHREADS / 32];
    __shared__ bool  isLast;

    const float KK = (float)((3.14159265358979323846 / 3.5) * (3.14159265358979323846 / 3.5));
    int tid = threadIdx.x;

    // Issue ALL stages up-front: 8 x 16B cp.async in flight per thread.
#pragma unroll
    for (int st = 0; st < QPT; st++) {
        int idx = blockIdx.x * RTHREADS + tid + st * (RBLOCKS * RTHREADS);
        cp16(&sbuf[st][0][tid], &g_src[idx]);
        cp16(&sbuf[st][1][tid], &g_tgt[idx]);
        CP_COMMIT();
    }

    // Table init overlaps the async loads.
    for (int i = tid; i < 256; i += RTHREADS) { s2tab[i] = 0.0f; ctab[i] = 0.0f; }
    __syncthreads();
    if (tid < 64) {
        int a = tid >> 3, b = tid & 7;
        int idx = (1 << a) + (1 << b) - 2;          // thermo(a)+thermo(b), perfect hash
        float g1 = a ? expf(-2.0f * KK * (float)(7 - a)) : 0.0f;
        float g2 = b ? expf(-2.0f * KK * (float)(7 - b)) : 0.0f;
        s2tab[idx] = g1 + g2;
        ctab[idx]  = (a && b) ? expf(-KK * (float)(14 - a - b)) : 0.0f;
    }
    __syncthreads();

    float a0 = 0.0f, a1 = 0.0f, a2 = 0.0f, a3 = 0.0f;
    const uint4 z4 = make_uint4(0u, 0u, 0u, 0u);

#pragma unroll
    for (int st = 0; st < QPT; st++) {
        if (st == 0) CP_WAIT(3);
        else if (st == 1) CP_WAIT(2);
        else if (st == 2) CP_WAIT(1);
        else CP_WAIT(0);

        uint4 s = sbuf[st][0][tid];
        uint4 t = sbuf[st][1][tid];
        unsigned sw[4] = { s.x, s.y, s.z, s.w };
        unsigned tw[4] = { t.x, t.y, t.z, t.w };

        // branchless src^2 term
#pragma unroll
        for (int l = 0; l < 4; l += 2) {
            unsigned k0 = __dp4a(sw[l],     0x00000101u, 0u);
            unsigned k1 = __dp4a(sw[l],     0x01010000u, 0u);
            unsigned k2 = __dp4a(sw[l + 1], 0x00000101u, 0u);
            unsigned k3 = __dp4a(sw[l + 1], 0x01010000u, 0u);
            a0 += s2tab[k0];
            a1 += s2tab[k1];
            a2 += s2tab[k2];
            a3 += s2tab[k3];
        }

        // cross term, rare
        unsigned uAny = (sw[0] & tw[0]) | (sw[1] & tw[1]) |
                        (sw[2] & tw[2]) | (sw[3] & tw[3]);
        if (uAny) {
#pragma unroll
            for (int l = 0; l < 4; l++) {
                unsigned kw = __vaddus4(sw[l], tw[l]);
                a0 -= ctab[kw & 255u];
                a1 -= ctab[(kw >> 8)  & 255u];
                a2 -= ctab[(kw >> 16) & 255u];
                a3 -= ctab[kw >> 24];
            }
        }

        // zero-stores for next replay (predicated)
        int idx = blockIdx.x * RTHREADS + tid + st * (RBLOCKS * RTHREADS);
        if (sw[0] | sw[1] | sw[2] | sw[3]) g_src[idx] = z4;
        if (tw[0] | tw[1] | tw[2] | tw[3]) g_tgt[idx] = z4;
    }

    float acc = (a0 + a1) + (a2 + a3);
#pragma unroll
    for (int off = 16; off > 0; off >>= 1)
        acc += __shfl_down_sync(0xFFFFFFFFu, acc, off);
    int warp = tid >> 5;
    if ((tid & 31) == 0) wsum[warp] = acc;
    __syncthreads();
    if (tid == 0) {
        float b = 0.0f;
#pragma unroll
        for (int wdx = 0; wdx < RTHREADS / 32; wdx++) b += wsum[wdx];
        g_part[blockIdx.x] = b;
        __threadfence();
        unsigned vdone = atomicAdd(&g_count, 1u);
        isLast = (vdone == (unsigned)gridDim.x - 1u);
        if (isLast) g_count = 0u;     // reset for next replay
    }
    __syncthreads();

    if (isLast) {
        double a = 0.0;
        for (int i = tid; i < RBLOCKS; i += RTHREADS)
            a += (double)g_part[i];
#pragma unroll
        for (int off = 16; off > 0; off >>= 1)
            a += __shfl_down_sync(0xFFFFFFFFu, a, off);
        if ((tid & 31) == 0) wsumd[warp] = a;
        __syncthreads();
        if (tid == 0) {
            double tot = 0.0;
#pragma unroll
            for (int wdx = 0; wdx < RTHREADS / 32; wdx++) tot += wsumd[wdx];
            out[0] = (float)tot;
        }
    }
}

extern "C" void kernel_launch(void* const* d_in, const int* in_sizes, int n_in,
                              void* d_out, int out_size)
{
    const float* src = (const float*)d_in[0];
    const float* tgt = (const float*)d_in[1];
    const float* ox  = (const float*)d_in[2];
    const float* oy  = (const float*)d_in[3];
    const float* oz  = (const float*)d_in[4];
    const float* vx  = (const float*)d_in[5];
    int N = in_sizes[0] / 3;

    int total = 2 * N * 5;
    int blocks = (total + 255) / 256;
    splat_kernel<<<blocks, 256>>>(src, tgt, ox, oy, oz, vx, N);
    reduce_kernel<<<RBLOCKS, RTHREADS>>>((float*)d_out);
}